// round 8
// baseline (speedup 1.0000x reference)
#include <cuda_runtime.h>
#include <cstdint>
#include <cfloat>

#define NROW 32768
#define NCOL 1024
#define DIM 64
#define ITERS 100
#define SINK_BLOCKS 148
#define XQ_ELEMS (NROW * DIM)          // 2097152
#define LOSS_OFF XQ_ELEMS
#define IDX_OFF (XQ_ELEMS + 1)

// k_sink dynamic smem: sC[1024] | sacc[16*1024] | sR[256] | sTrash[16]
#define SINK_SMEM_FLOATS (1024 + 16 * 1024 + 256 + 16)
#define SINK_SMEM_BYTES (SINK_SMEM_FLOATS * 4)   // 70720

// ---------------- device scratch (static: no runtime allocation) ----------------
__device__ float    g_P[(size_t)NROW * NCOL];     // d, then P' = exp(sc*(middle-d)); 134MB
__device__ float    g_xx[NROW];
__device__ float    g_ww[NCOL];
__device__ float    g_colsum[ITERS][NCOL];        // per-iteration column sums
__device__ int      g_idxQ[NROW];
__device__ int      g_idxD[NROW];
__device__ int      g_bad;
__device__ float    g_losspart[4096];
__device__ unsigned g_dmin_u, g_dmax_u;
__device__ unsigned g_barrier;
__device__ int      g_outcnt;

__device__ __forceinline__ unsigned fmapu(float f) {
    unsigned u = __float_as_uint(f);
    return (u & 0x80000000u) ? ~u : (u | 0x80000000u);
}
__device__ __forceinline__ float funmap(unsigned m) {
    unsigned v = (m & 0x80000000u) ? (m & 0x7fffffffu) : ~m;
    return __uint_as_float(v);
}

// FFMA-only exp (no MUFU). Identical to all passing rounds.
__device__ __forceinline__ float fexp(float x) {
    float t = x * 1.4426950408889634f;
    float r = rintf(t);
    float g = (t - r) * 0.6931471805599453f;
    float p = 1.0f + g * (1.0f + g * (0.5f + g * (0.16666666667f +
              g * (0.041666666667f + g * (0.0083333333333f + g * 0.0013888888889f)))));
    int ir = (int)r;
    float s = __int_as_float((ir + 127) << 23);
    return p * s;
}

// ---------------- 32-byte access helpers ----------------
struct F8 { float f[8]; };

__device__ __forceinline__ F8 ldg_evl8(const float* p) {   // keep in L2
    unsigned long long a, b, c, d;
    asm volatile("ld.global.nc.L2::evict_last.v4.b64 {%0,%1,%2,%3}, [%4];"
                 : "=l"(a), "=l"(b), "=l"(c), "=l"(d) : "l"(p));
    F8 r;
    r.f[0] = __uint_as_float((unsigned)a); r.f[1] = __uint_as_float((unsigned)(a >> 32));
    r.f[2] = __uint_as_float((unsigned)b); r.f[3] = __uint_as_float((unsigned)(b >> 32));
    r.f[4] = __uint_as_float((unsigned)c); r.f[5] = __uint_as_float((unsigned)(c >> 32));
    r.f[6] = __uint_as_float((unsigned)d); r.f[7] = __uint_as_float((unsigned)(d >> 32));
    return r;
}
__device__ __forceinline__ F8 ldg_cs8(const float* p) {    // stream through L2
    F8 r;
    float4 a = __ldcs((const float4*)p);
    float4 b = __ldcs((const float4*)p + 1);
    r.f[0] = a.x; r.f[1] = a.y; r.f[2] = a.z; r.f[3] = a.w;
    r.f[4] = b.x; r.f[5] = b.y; r.f[6] = b.z; r.f[7] = b.w;
    return r;
}
__device__ __forceinline__ void stg_evl8(float* p, const F8& v) {
    unsigned long long a = (unsigned long long)__float_as_uint(v.f[0]) |
                           ((unsigned long long)__float_as_uint(v.f[1]) << 32);
    unsigned long long b = (unsigned long long)__float_as_uint(v.f[2]) |
                           ((unsigned long long)__float_as_uint(v.f[3]) << 32);
    unsigned long long c = (unsigned long long)__float_as_uint(v.f[4]) |
                           ((unsigned long long)__float_as_uint(v.f[5]) << 32);
    unsigned long long d = (unsigned long long)__float_as_uint(v.f[6]) |
                           ((unsigned long long)__float_as_uint(v.f[7]) << 32);
    asm volatile("st.global.L2::evict_last.v4.b64 [%0], {%1,%2,%3,%4};"
                 :: "l"(p), "l"(a), "l"(b), "l"(c), "l"(d) : "memory");
}
__device__ __forceinline__ void stg_cs8(float* p, const F8& v) {
    __stcs((float4*)p,     make_float4(v.f[0], v.f[1], v.f[2], v.f[3]));
    __stcs((float4*)p + 1, make_float4(v.f[4], v.f[5], v.f[6], v.f[7]));
}
__device__ __forceinline__ void pf_l2(const float* p) {    // fire-and-forget prefetch
    asm volatile("prefetch.global.L2 [%0];" :: "l"(p));
}

// streamed-row predicate: 8/16 pinned, 8/16 streamed+prefetched
__device__ __forceinline__ bool pinned_row(int r) { return (r & 15) < 8; }

// ---------------- init: norms + colsum zero + scalars ----------------
__global__ void k_init0(const float* __restrict__ x, const float* __restrict__ W) {
    int tid = threadIdx.x;
    if (blockIdx.x < 4224) {
        int gw = blockIdx.x * 8 + (tid >> 5);
        int lane = tid & 31;
        if (gw >= NROW + NCOL) return;
        const float* src = (gw < NROW) ? (x + (size_t)gw * DIM)
                                       : (W + (size_t)(gw - NROW) * DIM);
        float2 v = ((const float2*)src)[lane];
        float s = v.x * v.x + v.y * v.y;
#pragma unroll
        for (int o = 16; o; o >>= 1) s += __shfl_xor_sync(0xffffffffu, s, o);
        if (lane == 0) {
            if (gw < NROW) g_xx[gw] = s;
            else           g_ww[gw - NROW] = s;
        }
    } else {
        int i = (blockIdx.x - 4224) * 256 + tid;
        if (i < ITERS * NCOL) ((float*)g_colsum)[i] = 0.0f;
        if (blockIdx.x == 4224 && tid == 0) {
            g_barrier = 0u;
            g_bad = 0;
            g_outcnt = 0;
            g_dmin_u = 0xFFFFFFFFu;
            g_dmax_u = 0u;
        }
    }
}

// ---------------- d = xx + ww - 2 x@W^T; global min/max of d ----------------
__global__ void __launch_bounds__(256) k_gemm(const float* __restrict__ x,
                                              const float* __restrict__ W) {
    __shared__ float xsT[64][68];
    __shared__ float wsT[64][68];
    int tid = threadIdx.x;
    int r0 = blockIdx.x * 64;
    int c0 = blockIdx.y * 64;

    for (int n = tid; n < 1024; n += 256) {
        int r = n >> 4, d4 = (n & 15) << 2;
        float4 v = *(const float4*)(x + (size_t)(r0 + r) * DIM + d4);
        xsT[d4 + 0][r] = v.x; xsT[d4 + 1][r] = v.y;
        xsT[d4 + 2][r] = v.z; xsT[d4 + 3][r] = v.w;
        float4 u = *(const float4*)(W + (size_t)(c0 + r) * DIM + d4);
        wsT[d4 + 0][r] = u.x; wsT[d4 + 1][r] = u.y;
        wsT[d4 + 2][r] = u.z; wsT[d4 + 3][r] = u.w;
    }
    __syncthreads();

    int tx = tid & 15, ty = tid >> 4;
    float acc[4][4];
#pragma unroll
    for (int i = 0; i < 4; ++i)
#pragma unroll
        for (int j = 0; j < 4; ++j) acc[i][j] = 0.0f;

#pragma unroll 8
    for (int d = 0; d < 64; ++d) {
        float4 a = *(const float4*)&xsT[d][ty * 4];
        float4 b = *(const float4*)&wsT[d][tx * 4];
        float av[4] = {a.x, a.y, a.z, a.w};
        float bv[4] = {b.x, b.y, b.z, b.w};
#pragma unroll
        for (int i = 0; i < 4; ++i)
#pragma unroll
            for (int j = 0; j < 4; ++j) acc[i][j] += av[i] * bv[j];
    }

    float mn = FLT_MAX, mx = -FLT_MAX;
#pragma unroll
    for (int i = 0; i < 4; ++i) {
        int row = r0 + ty * 4 + i;
        float xxv = g_xx[row];
        float dv[4];
#pragma unroll
        for (int j = 0; j < 4; ++j) {
            dv[j] = (xxv + g_ww[c0 + tx * 4 + j]) - 2.0f * acc[i][j];
            mn = fminf(mn, dv[j]);
            mx = fmaxf(mx, dv[j]);
        }
        *(float4*)(g_P + (size_t)row * NCOL + c0 + tx * 4) =
            make_float4(dv[0], dv[1], dv[2], dv[3]);
    }

    __shared__ float smn[256], smx[256];
    smn[tid] = mn; smx[tid] = mx;
    __syncthreads();
    for (int s = 128; s; s >>= 1) {
        if (tid < s) {
            smn[tid] = fminf(smn[tid], smn[tid + s]);
            smx[tid] = fmaxf(smx[tid], smx[tid + s]);
        }
        __syncthreads();
    }
    if (tid == 0) {
        atomicMin(&g_dmin_u, fmapu(smn[0]));
        atomicMax(&g_dmax_u, fmapu(smx[0]));
    }
}

// ---------------- persistent Sinkhorn: 148 blocks (all SMs), uneven rows ----------------
// block b owns rows [rstart, rstart+nrows), nrows = 221 or 222; warp w owns an
// even-split slice [ws, we). Pair-processing hot loop (8 loads in flight, two
// interleaved shuffle chains). 8/16 rows pinned in L2 (evict_last, 67MB); the
// other 8/16 streamed (.cs) and prefetched back into L2 each iteration during
// the reduction/barrier tail so the next pass hits L2.
__global__ void __launch_bounds__(512, 1) k_sink() {
    extern __shared__ float sm[];
    float* sC     = sm;                      // [1024]
    float* sacc   = sm + 1024;               // [16][1024] per-warp column partials
    float* sR     = sm + 1024 + 16 * 1024;   // [256] last-iter row factors (local idx)
    float* sTrash = sR + 256;                // [16] never-taken sink

    int tid = threadIdx.x, lane = tid & 31, w = tid >> 5;
    int b = blockIdx.x;
    int rstart = b * 221 + min(b, 60);
    int nrows = 221 + (b < 60 ? 1 : 0);
    int ws = rstart + (nrows * w) / 16;
    int we = rstart + (nrows * (w + 1)) / 16;
    unsigned phase = 0;

    // constants derived redundantly per block (k_gemm finished before this launch)
    float mn = funmap(g_dmin_u);
    float mx = funmap(g_dmax_u);
    float mid = (mx + mn) * 0.5f;
    float sc = 1.0f / ((mx - mid + 1e-5f) * 0.05f);

    for (int j = tid; j < NCOL; j += 512) sC[j] = 1.0f;   // C^(0) = 1
    __syncthreads();

    F8 racc[4];
#pragma unroll
    for (int q = 0; q < 4; ++q)
#pragma unroll
        for (int e = 0; e < 8; ++e) racc[q].f[e] = 0.0f;

    // ---- pre-phase == transform + iteration 0 (C=1) ----
    for (int r = ws; r < we; ++r) {
        float* pr = g_P + (size_t)r * NCOL;
        F8 p[4];
#pragma unroll
        for (int q = 0; q < 4; ++q) {
            F8 v = ldg_cs8(pr + lane * 8 + 256 * q);
#pragma unroll
            for (int e = 0; e < 8; ++e) v.f[e] = fexp((mid - v.f[e]) * sc);
            p[q] = v;
        }
        if (pinned_row(r)) {
#pragma unroll
            for (int q = 0; q < 4; ++q) stg_evl8(pr + lane * 8 + 256 * q, p[q]);
        } else {
#pragma unroll
            for (int q = 0; q < 4; ++q) stg_cs8(pr + lane * 8 + 256 * q, p[q]);
        }
        float dot = 0.0f;
#pragma unroll
        for (int q = 0; q < 4; ++q)
            dot += p[q].f[0] + p[q].f[1] + p[q].f[2] + p[q].f[3]
                 + p[q].f[4] + p[q].f[5] + p[q].f[6] + p[q].f[7];
#pragma unroll
        for (int o = 16; o; o >>= 1) dot += __shfl_xor_sync(0xffffffffu, dot, o);
        float R = 1.0f / (32768.0f * dot);
#pragma unroll
        for (int q = 0; q < 4; ++q)
#pragma unroll
            for (int e = 0; e < 8; ++e) racc[q].f[e] += R * p[q].f[e];
        if (lane == 0) sR[r - rstart] = R;
    }

    // ---- iterations; t==0 uses the pre-phase racc ----
    for (int t = 0; t < ITERS; ++t) {
        if (t > 0) {
#pragma unroll
            for (int q = 0; q < 4; ++q)
#pragma unroll
                for (int e = 0; e < 8; ++e) racc[q].f[e] = 0.0f;

            int r = ws;
            for (; r + 1 < we; r += 2) {               // row pairs
                const float* pa = g_P + (size_t)r * NCOL;
                const float* pb = pa + NCOL;
                bool pina = pinned_row(r), pinb = pinned_row(r + 1);
                F8 A[4], B[4];
#pragma unroll
                for (int q = 0; q < 4; ++q) {
                    if (pina) A[q] = ldg_evl8(pa + lane * 8 + 256 * q);
                    else      A[q] = ldg_cs8(pa + lane * 8 + 256 * q);
                    if (pinb) B[q] = ldg_evl8(pb + lane * 8 + 256 * q);
                    else      B[q] = ldg_cs8(pb + lane * 8 + 256 * q);
                }
                float dota = 0.0f, dotb = 0.0f;
#pragma unroll
                for (int q = 0; q < 4; ++q) {
                    const float* cv = sC + lane * 8 + 256 * q;
                    float4 c0 = *(const float4*)cv;
                    float4 c1 = *(const float4*)(cv + 4);
                    dota += A[q].f[0] * c0.x + A[q].f[1] * c0.y + A[q].f[2] * c0.z + A[q].f[3] * c0.w
                          + A[q].f[4] * c1.x + A[q].f[5] * c1.y + A[q].f[6] * c1.z + A[q].f[7] * c1.w;
                    dotb += B[q].f[0] * c0.x + B[q].f[1] * c0.y + B[q].f[2] * c0.z + B[q].f[3] * c0.w
                          + B[q].f[4] * c1.x + B[q].f[5] * c1.y + B[q].f[6] * c1.z + B[q].f[7] * c1.w;
                }
#pragma unroll
                for (int o = 16; o; o >>= 1) {
                    dota += __shfl_xor_sync(0xffffffffu, dota, o);
                    dotb += __shfl_xor_sync(0xffffffffu, dotb, o);
                }
                float Ra = 1.0f / (32768.0f * dota);
                float Rb = 1.0f / (32768.0f * dotb);
#pragma unroll
                for (int q = 0; q < 4; ++q)
#pragma unroll
                    for (int e = 0; e < 8; ++e) racc[q].f[e] += Ra * A[q].f[e];
#pragma unroll
                for (int q = 0; q < 4; ++q)
#pragma unroll
                    for (int e = 0; e < 8; ++e) racc[q].f[e] += Rb * B[q].f[e];
                if (lane == 0) {
                    sR[r - rstart]     = Ra;
                    sR[r + 1 - rstart] = Rb;
                }
            }
            if (r < we) {                               // leftover single row
                const float* pa = g_P + (size_t)r * NCOL;
                F8 A[4];
#pragma unroll
                for (int q = 0; q < 4; ++q)
                    A[q] = pinned_row(r) ? ldg_evl8(pa + lane * 8 + 256 * q)
                                         : ldg_cs8(pa + lane * 8 + 256 * q);
                float dota = 0.0f;
#pragma unroll
                for (int q = 0; q < 4; ++q) {
                    const float* cv = sC + lane * 8 + 256 * q;
                    float4 c0 = *(const float4*)cv;
                    float4 c1 = *(const float4*)(cv + 4);
                    dota += A[q].f[0] * c0.x + A[q].f[1] * c0.y + A[q].f[2] * c0.z + A[q].f[3] * c0.w
                          + A[q].f[4] * c1.x + A[q].f[5] * c1.y + A[q].f[6] * c1.z + A[q].f[7] * c1.w;
                }
#pragma unroll
                for (int o = 16; o; o >>= 1) dota += __shfl_xor_sync(0xffffffffu, dota, o);
                float Ra = 1.0f / (32768.0f * dota);
#pragma unroll
                for (int q = 0; q < 4; ++q)
#pragma unroll
                    for (int e = 0; e < 8; ++e) racc[q].f[e] += Ra * A[q].f[e];
                if (lane == 0) sR[r - rstart] = Ra;
            }
        }

        // stage warp partials to smem
#pragma unroll
        for (int q = 0; q < 4; ++q) {
            float* dst = sacc + w * NCOL + lane * 8 + 256 * q;
            *(float4*)dst       = make_float4(racc[q].f[0], racc[q].f[1], racc[q].f[2], racc[q].f[3]);
            *(float4*)(dst + 4) = make_float4(racc[q].f[4], racc[q].f[5], racc[q].f[6], racc[q].f[7]);
        }
        __syncthreads();

        // prefetch streamed rows back into L2 for the next pass (fire-and-forget;
        // DRAM streams them during the reduction + barrier + early next iter)
        for (int r = ws; r < we; ++r) {
            if (!pinned_row(r)) {
                const float* pr = g_P + (size_t)r * NCOL + lane * 8;
#pragma unroll
                for (int q = 0; q < 4; ++q) pf_l2(pr + 256 * q);
            }
        }

        // block reduction + global RED
        float dummy = 0.0f;
        for (int j = tid; j < NCOL; j += 512) {
            float s = 0.0f;
#pragma unroll
            for (int ww = 0; ww < 16; ++ww) s += sacc[ww * NCOL + j];
            dummy += atomicAdd(&g_colsum[t][j], s);
        }
        // completion fence: consuming atomic returns guarantees REDs performed at L2
        if (__float_as_uint(dummy) == 0x7F800123u) sTrash[w] = dummy;
        __syncthreads();
        if (tid == 0) {
            unsigned arrived = atomicAdd(&g_barrier, 1u) + 1u;
            phase += SINK_BLOCKS;
            if (arrived < phase) {
                while (*(volatile unsigned*)&g_barrier < phase) __nanosleep(32);
            }
        }
        __syncthreads();

        for (int j = tid; j < NCOL; j += 512)
            sC[j] = 1.0f / (1024.0f * __ldcg(&g_colsum[t][j]));
        __syncthreads();
    }

    // ---- fused final pass: argmax(P'*C_final), argmax(P') (== argmin d), finiteness ----
    for (int r = ws; r < we; ++r) {
        const float* pr = g_P + (size_t)r * NCOL;
        float rb = sR[r - rstart] * 32768.0f;

        float bq = -FLT_MAX; int biq = 0;
        float bp = -FLT_MAX; int bip = 0;
        bool bad = false;
#pragma unroll
        for (int q = 0; q < 4; ++q) {
            F8 p = pinned_row(r) ? ldg_evl8(pr + lane * 8 + 256 * q)
                                 : ldg_cs8(pr + lane * 8 + 256 * q);
            const float* cv = sC + lane * 8 + 256 * q;
            int jb = lane * 8 + 256 * q;
#pragma unroll
            for (int e = 0; e < 8; ++e) {
                float qv = p.f[e] * cv[e];
                float full = qv * rb;
                if (!(fabsf(full) <= FLT_MAX)) bad = true;
                if (qv > bq) { bq = qv; biq = jb + e; }
                if (p.f[e] > bp) { bp = p.f[e]; bip = jb + e; }
            }
        }
#pragma unroll
        for (int o = 16; o; o >>= 1) {
            float ov = __shfl_xor_sync(0xffffffffu, bq, o);
            int   oi = __shfl_xor_sync(0xffffffffu, biq, o);
            if (ov > bq || (ov == bq && oi < biq)) { bq = ov; biq = oi; }
            ov = __shfl_xor_sync(0xffffffffu, bp, o);
            oi = __shfl_xor_sync(0xffffffffu, bip, o);
            if (ov > bp || (ov == bp && oi < bip)) { bp = ov; bip = oi; }
        }
        bool anybad = __any_sync(0xffffffffu, bad);
        if (lane == 0) {
            g_idxQ[r] = biq;
            g_idxD[r] = bip;
            if (anybad) atomicOr(&g_bad, 1);
        }
    }
}

// ---------------- output: x_q_st rows, indices, loss (fused last-block reduce) -----------
__global__ void k_output(const float* __restrict__ x, const float* __restrict__ W,
                         float* __restrict__ out) {
    __shared__ float spart[8];
    __shared__ float sred[256];
    __shared__ int   slast;
    int tid = threadIdx.x, lane = tid & 31, w = tid >> 5;
    int row = blockIdx.x * 8 + w;
    int idx = g_bad ? g_idxD[row] : g_idxQ[row];

    float2 wv = ((const float2*)(W + (size_t)idx * DIM))[lane];
    float2 xv = ((const float2*)(x + (size_t)row * DIM))[lane];
    float dx = wv.x - xv.x, dy = wv.y - xv.y;
    float2 st = make_float2(xv.x + dx, xv.y + dy);   // x + (x_q - x)
    ((float2*)(out + (size_t)row * DIM))[lane] = st;

    float s = dx * dx + dy * dy;
#pragma unroll
    for (int o = 16; o; o >>= 1) s += __shfl_xor_sync(0xffffffffu, s, o);
    if (lane == 0) {
        spart[w] = s;
        out[IDX_OFF + row] = (float)idx;
    }
    __syncthreads();
    if (tid == 0) {
        float t = 0.f;
#pragma unroll
        for (int i = 0; i < 8; ++i) t += spart[i];
        g_losspart[blockIdx.x] = t;
        __threadfence();
        slast = (atomicAdd(&g_outcnt, 1) == 4095) ? 1 : 0;
    }
    __syncthreads();

    if (slast) {
        float acc = 0.f;
        for (int i = tid; i < 4096; i += 256) acc += __ldcg(&g_losspart[i]);
        sred[tid] = acc;
        __syncthreads();
        for (int o = 128; o; o >>= 1) {
            if (tid < o) sred[tid] += sred[tid + o];
            __syncthreads();
        }
        if (tid == 0) {
            float m = sred[0] / (float)XQ_ELEMS;
            out[LOSS_OFF] = m + 0.25f * m;
            g_outcnt = 0;                 // reset for next graph replay
        }
    }
}

extern "C" void kernel_launch(void* const* d_in, const int* in_sizes, int n_in,
                              void* d_out, int out_size) {
    const float* x = (const float*)d_in[0];
    const float* W = (const float*)d_in[1];
    float* out = (float*)d_out;

    static bool attr_set = false;
    if (!attr_set) {
        cudaFuncSetAttribute(k_sink, cudaFuncAttributeMaxDynamicSharedMemorySize,
                             SINK_SMEM_BYTES);
        attr_set = true;
    }

    k_init0<<<4624, 256>>>(x, W);
    k_gemm<<<dim3(512, 16), 256>>>(x, W);
    k_sink<<<SINK_BLOCKS, 512, SINK_SMEM_BYTES>>>();
    k_output<<<4096, 256>>>(x, W, out);
}

// round 9
// speedup vs baseline: 1.0211x; 1.0211x over previous
#include <cuda_runtime.h>
#include <cstdint>
#include <cfloat>

#define NROW 32768
#define NCOL 1024
#define DIM 64
#define ITERS 100
#define SINK_BLOCKS 128
#define XQ_ELEMS (NROW * DIM)          // 2097152
#define LOSS_OFF XQ_ELEMS
#define IDX_OFF (XQ_ELEMS + 1)

// k_sink dynamic smem: sC[1024] | sacc[16*1024] | sR[256] | sTrash[16]
#define SINK_SMEM_FLOATS (1024 + 16 * 1024 + 256 + 16)
#define SINK_SMEM_BYTES (SINK_SMEM_FLOATS * 4)   // 70720

// ---------------- device scratch (static: no runtime allocation) ----------------
__device__ float    g_P[(size_t)NROW * NCOL];     // d, then P' = exp(sc*(middle-d)); 134MB
__device__ float    g_xx[NROW];
__device__ float    g_ww[NCOL];
__device__ float    g_colsum[ITERS][NCOL];        // per-iteration column sums
__device__ int      g_idxQ[NROW];
__device__ int      g_idxD[NROW];
__device__ int      g_bad;
__device__ float    g_losspart[4096];
__device__ unsigned g_dmin_u, g_dmax_u;
__device__ unsigned g_barrier;
__device__ int      g_outcnt;

__device__ __forceinline__ unsigned fmapu(float f) {
    unsigned u = __float_as_uint(f);
    return (u & 0x80000000u) ? ~u : (u | 0x80000000u);
}
__device__ __forceinline__ float funmap(unsigned m) {
    unsigned v = (m & 0x80000000u) ? (m & 0x7fffffffu) : ~m;
    return __uint_as_float(v);
}

// FFMA-only exp (no MUFU). Identical to all passing rounds.
__device__ __forceinline__ float fexp(float x) {
    float t = x * 1.4426950408889634f;
    float r = rintf(t);
    float g = (t - r) * 0.6931471805599453f;
    float p = 1.0f + g * (1.0f + g * (0.5f + g * (0.16666666667f +
              g * (0.041666666667f + g * (0.0083333333333f + g * 0.0013888888889f)))));
    int ir = (int)r;
    float s = __int_as_float((ir + 127) << 23);
    return p * s;
}

// ---------------- 32-byte access helpers ----------------
struct F8 { float f[8]; };

__device__ __forceinline__ F8 ldg_evl8(const float* p) {   // keep in L2
    unsigned long long a, b, c, d;
    asm volatile("ld.global.nc.L2::evict_last.v4.b64 {%0,%1,%2,%3}, [%4];"
                 : "=l"(a), "=l"(b), "=l"(c), "=l"(d) : "l"(p));
    F8 r;
    r.f[0] = __uint_as_float((unsigned)a); r.f[1] = __uint_as_float((unsigned)(a >> 32));
    r.f[2] = __uint_as_float((unsigned)b); r.f[3] = __uint_as_float((unsigned)(b >> 32));
    r.f[4] = __uint_as_float((unsigned)c); r.f[5] = __uint_as_float((unsigned)(c >> 32));
    r.f[6] = __uint_as_float((unsigned)d); r.f[7] = __uint_as_float((unsigned)(d >> 32));
    return r;
}
__device__ __forceinline__ F8 ldg_cs8(const float* p) {    // stream through L2
    F8 r;
    float4 a = __ldcs((const float4*)p);
    float4 b = __ldcs((const float4*)p + 1);
    r.f[0] = a.x; r.f[1] = a.y; r.f[2] = a.z; r.f[3] = a.w;
    r.f[4] = b.x; r.f[5] = b.y; r.f[6] = b.z; r.f[7] = b.w;
    return r;
}
__device__ __forceinline__ void stg_evl8(float* p, const F8& v) {
    unsigned long long a = (unsigned long long)__float_as_uint(v.f[0]) |
                           ((unsigned long long)__float_as_uint(v.f[1]) << 32);
    unsigned long long b = (unsigned long long)__float_as_uint(v.f[2]) |
                           ((unsigned long long)__float_as_uint(v.f[3]) << 32);
    unsigned long long c = (unsigned long long)__float_as_uint(v.f[4]) |
                           ((unsigned long long)__float_as_uint(v.f[5]) << 32);
    unsigned long long d = (unsigned long long)__float_as_uint(v.f[6]) |
                           ((unsigned long long)__float_as_uint(v.f[7]) << 32);
    asm volatile("st.global.L2::evict_last.v4.b64 [%0], {%1,%2,%3,%4};"
                 :: "l"(p), "l"(a), "l"(b), "l"(c), "l"(d) : "memory");
}
__device__ __forceinline__ void stg_cs8(float* p, const F8& v) {
    __stcs((float4*)p,     make_float4(v.f[0], v.f[1], v.f[2], v.f[3]));
    __stcs((float4*)p + 1, make_float4(v.f[4], v.f[5], v.f[6], v.f[7]));
}

// ---------------- init: norms + colsum zero + scalars ----------------
__global__ void k_init0(const float* __restrict__ x, const float* __restrict__ W) {
    int tid = threadIdx.x;
    if (blockIdx.x < 4224) {
        int gw = blockIdx.x * 8 + (tid >> 5);
        int lane = tid & 31;
        if (gw >= NROW + NCOL) return;
        const float* src = (gw < NROW) ? (x + (size_t)gw * DIM)
                                       : (W + (size_t)(gw - NROW) * DIM);
        float2 v = ((const float2*)src)[lane];
        float s = v.x * v.x + v.y * v.y;
#pragma unroll
        for (int o = 16; o; o >>= 1) s += __shfl_xor_sync(0xffffffffu, s, o);
        if (lane == 0) {
            if (gw < NROW) g_xx[gw] = s;
            else           g_ww[gw - NROW] = s;
        }
    } else {
        int i = (blockIdx.x - 4224) * 256 + tid;
        if (i < ITERS * NCOL) ((float*)g_colsum)[i] = 0.0f;
        if (blockIdx.x == 4224 && tid == 0) {
            g_barrier = 0u;
            g_bad = 0;
            g_outcnt = 0;
            g_dmin_u = 0xFFFFFFFFu;
            g_dmax_u = 0u;
        }
    }
}

// ---------------- d = xx + ww - 2 x@W^T; global min/max of d ----------------
__global__ void __launch_bounds__(256) k_gemm(const float* __restrict__ x,
                                              const float* __restrict__ W) {
    __shared__ float xsT[64][68];
    __shared__ float wsT[64][68];
    int tid = threadIdx.x;
    int r0 = blockIdx.x * 64;
    int c0 = blockIdx.y * 64;

    for (int n = tid; n < 1024; n += 256) {
        int r = n >> 4, d4 = (n & 15) << 2;
        float4 v = *(const float4*)(x + (size_t)(r0 + r) * DIM + d4);
        xsT[d4 + 0][r] = v.x; xsT[d4 + 1][r] = v.y;
        xsT[d4 + 2][r] = v.z; xsT[d4 + 3][r] = v.w;
        float4 u = *(const float4*)(W + (size_t)(c0 + r) * DIM + d4);
        wsT[d4 + 0][r] = u.x; wsT[d4 + 1][r] = u.y;
        wsT[d4 + 2][r] = u.z; wsT[d4 + 3][r] = u.w;
    }
    __syncthreads();

    int tx = tid & 15, ty = tid >> 4;
    float acc[4][4];
#pragma unroll
    for (int i = 0; i < 4; ++i)
#pragma unroll
        for (int j = 0; j < 4; ++j) acc[i][j] = 0.0f;

#pragma unroll 8
    for (int d = 0; d < 64; ++d) {
        float4 a = *(const float4*)&xsT[d][ty * 4];
        float4 b = *(const float4*)&wsT[d][tx * 4];
        float av[4] = {a.x, a.y, a.z, a.w};
        float bv[4] = {b.x, b.y, b.z, b.w};
#pragma unroll
        for (int i = 0; i < 4; ++i)
#pragma unroll
            for (int j = 0; j < 4; ++j) acc[i][j] += av[i] * bv[j];
    }

    float mn = FLT_MAX, mx = -FLT_MAX;
#pragma unroll
    for (int i = 0; i < 4; ++i) {
        int row = r0 + ty * 4 + i;
        float xxv = g_xx[row];
        float dv[4];
#pragma unroll
        for (int j = 0; j < 4; ++j) {
            dv[j] = (xxv + g_ww[c0 + tx * 4 + j]) - 2.0f * acc[i][j];
            mn = fminf(mn, dv[j]);
            mx = fmaxf(mx, dv[j]);
        }
        *(float4*)(g_P + (size_t)row * NCOL + c0 + tx * 4) =
            make_float4(dv[0], dv[1], dv[2], dv[3]);
    }

    __shared__ float smn[256], smx[256];
    smn[tid] = mn; smx[tid] = mx;
    __syncthreads();
    for (int s = 128; s; s >>= 1) {
        if (tid < s) {
            smn[tid] = fminf(smn[tid], smn[tid + s]);
            smx[tid] = fmaxf(smx[tid], smx[tid + s]);
        }
        __syncthreads();
    }
    if (tid == 0) {
        atomicMin(&g_dmin_u, fmapu(smn[0]));
        atomicMax(&g_dmax_u, fmapu(smx[0]));
    }
}

// ---------------- persistent Sinkhorn (R7 structure) + early exit ----------------
// Block owns 256 contiguous rows; warp w owns rows [16w, 16w+16).
//   (row mod 16) < 11 : pinned in L2 (evict_last, 88MB chip-wide)
//   else              : streamed (.cs, 46MB DRAM/iter)
// Early exit: when max_j |dC_j| <= 2e-7*|C_j| the remaining iterations are a
// sub-ulp-tail no-op; all blocks compute the identical decision from identical
// g_colsum values, so no extra synchronization is needed.
__global__ void __launch_bounds__(512, 1) k_sink() {
    extern __shared__ float sm[];
    float* sC     = sm;                      // [1024]
    float* sacc   = sm + 1024;               // [16][1024] per-warp column partials
    float* sR     = sm + 1024 + 16 * 1024;   // [256] last-iter row factors
    float* sTrash = sR + 256;                // [16] never-taken sink
    __shared__ int sdiff;

    int tid = threadIdx.x, lane = tid & 31, w = tid >> 5;
    int r0 = blockIdx.x * 256;
    unsigned phase = 0;

    // constants derived redundantly per block (k_gemm completed before launch)
    float mnv = funmap(g_dmin_u);
    float mxv = funmap(g_dmax_u);
    float mid = (mxv + mnv) * 0.5f;
    float sc = 1.0f / ((mxv - mid + 1e-5f) * 0.05f);

    for (int j = tid; j < NCOL; j += 512) sC[j] = 1.0f;   // C^(0) = 1
    __syncthreads();

    F8 racc[4];
#pragma unroll
    for (int q = 0; q < 4; ++q)
#pragma unroll
        for (int e = 0; e < 8; ++e) racc[q].f[e] = 0.0f;

    // ---- pre-phase == transform + iteration 0 (C=1): read d, P'=fexp, store, dot ----
#pragma unroll
    for (int rr = 0; rr < 16; ++rr) {
        int row = r0 + w * 16 + rr;
        float* pr = g_P + (size_t)row * NCOL;
        F8 p[4];
#pragma unroll
        for (int q = 0; q < 4; ++q) {
            F8 v = ldg_cs8(pr + lane * 8 + 256 * q);
#pragma unroll
            for (int e = 0; e < 8; ++e) v.f[e] = fexp((mid - v.f[e]) * sc);
            p[q] = v;
        }
        if (rr < 11) {
#pragma unroll
            for (int q = 0; q < 4; ++q) stg_evl8(pr + lane * 8 + 256 * q, p[q]);
        } else {
#pragma unroll
            for (int q = 0; q < 4; ++q) stg_cs8(pr + lane * 8 + 256 * q, p[q]);
        }
        float dot = 0.0f;
#pragma unroll
        for (int q = 0; q < 4; ++q)
            dot += p[q].f[0] + p[q].f[1] + p[q].f[2] + p[q].f[3]
                 + p[q].f[4] + p[q].f[5] + p[q].f[6] + p[q].f[7];
#pragma unroll
        for (int o = 16; o; o >>= 1) dot += __shfl_xor_sync(0xffffffffu, dot, o);
        float R = 1.0f / (32768.0f * dot);
#pragma unroll
        for (int q = 0; q < 4; ++q)
#pragma unroll
            for (int e = 0; e < 8; ++e) racc[q].f[e] += R * p[q].f[e];
        if (lane == 0) sR[w * 16 + rr] = R;
    }

    // ---- iterations; t==0 uses the pre-phase racc ----
    for (int t = 0; t < ITERS; ++t) {
        if (t > 0) {
#pragma unroll
            for (int q = 0; q < 4; ++q)
#pragma unroll
                for (int e = 0; e < 8; ++e) racc[q].f[e] = 0.0f;

#pragma unroll
            for (int rp = 0; rp < 8; ++rp) {            // row PAIRS (2*rp, 2*rp+1)
                int ra = r0 + w * 16 + 2 * rp;
                const float* pa = g_P + (size_t)ra * NCOL;
                const float* pb = pa + NCOL;
                F8 A[4], B[4];
#pragma unroll
                for (int q = 0; q < 4; ++q) {
                    if (2 * rp < 11)     A[q] = ldg_evl8(pa + lane * 8 + 256 * q);
                    else                 A[q] = ldg_cs8(pa + lane * 8 + 256 * q);
                    if (2 * rp + 1 < 11) B[q] = ldg_evl8(pb + lane * 8 + 256 * q);
                    else                 B[q] = ldg_cs8(pb + lane * 8 + 256 * q);
                }
                float dota = 0.0f, dotb = 0.0f;
#pragma unroll
                for (int q = 0; q < 4; ++q) {
                    const float* cv = sC + lane * 8 + 256 * q;
                    float4 c0 = *(const float4*)cv;
                    float4 c1 = *(const float4*)(cv + 4);
                    dota += A[q].f[0] * c0.x + A[q].f[1] * c0.y + A[q].f[2] * c0.z + A[q].f[3] * c0.w
                          + A[q].f[4] * c1.x + A[q].f[5] * c1.y + A[q].f[6] * c1.z + A[q].f[7] * c1.w;
                    dotb += B[q].f[0] * c0.x + B[q].f[1] * c0.y + B[q].f[2] * c0.z + B[q].f[3] * c0.w
                          + B[q].f[4] * c1.x + B[q].f[5] * c1.y + B[q].f[6] * c1.z + B[q].f[7] * c1.w;
                }
#pragma unroll
                for (int o = 16; o; o >>= 1) {
                    dota += __shfl_xor_sync(0xffffffffu, dota, o);
                    dotb += __shfl_xor_sync(0xffffffffu, dotb, o);
                }
                float Ra = 1.0f / (32768.0f * dota);
                float Rb = 1.0f / (32768.0f * dotb);
#pragma unroll
                for (int q = 0; q < 4; ++q)
#pragma unroll
                    for (int e = 0; e < 8; ++e) racc[q].f[e] += Ra * A[q].f[e];
#pragma unroll
                for (int q = 0; q < 4; ++q)
#pragma unroll
                    for (int e = 0; e < 8; ++e) racc[q].f[e] += Rb * B[q].f[e];
                if (lane == 0) {
                    sR[w * 16 + 2 * rp]     = Ra;
                    sR[w * 16 + 2 * rp + 1] = Rb;
                }
            }
        }

        // deterministic staged reduction: warp partials -> smem -> global RED
#pragma unroll
        for (int q = 0; q < 4; ++q) {
            float* dst = sacc + w * NCOL + lane * 8 + 256 * q;
            *(float4*)dst       = make_float4(racc[q].f[0], racc[q].f[1], racc[q].f[2], racc[q].f[3]);
            *(float4*)(dst + 4) = make_float4(racc[q].f[4], racc[q].f[5], racc[q].f[6], racc[q].f[7]);
        }
        __syncthreads();
        if (tid == 0) sdiff = 0;   // reset convergence flag (pre-barrier)
        float dummy = 0.0f;
        for (int j = tid; j < NCOL; j += 512) {
            float s = 0.0f;
#pragma unroll
            for (int ww = 0; ww < 16; ++ww) s += sacc[ww * NCOL + j];
            dummy += atomicAdd(&g_colsum[t][j], s);
        }
        // completion fence: consuming atomic returns guarantees REDs performed at L2
        if (__float_as_uint(dummy) == 0x7F800123u) sTrash[w] = dummy;
        __syncthreads();
        if (tid == 0) {
            unsigned arrived = atomicAdd(&g_barrier, 1u) + 1u;
            phase += SINK_BLOCKS;
            if (arrived < phase) {
                while (*(volatile unsigned*)&g_barrier < phase) __nanosleep(32);
            }
        }
        __syncthreads();

        // update C; convergence test (identical decision in every block)
        int mydiff = 0;
        for (int j = tid; j < NCOL; j += 512) {
            float oldc = sC[j];
            float newc = 1.0f / (1024.0f * __ldcg(&g_colsum[t][j]));
            sC[j] = newc;
            if (fabsf(newc - oldc) > 2e-7f * fabsf(oldc)) mydiff = 1;
        }
        if (mydiff) sdiff = 1;
        __syncthreads();
        if (t < ITERS - 1 && sdiff == 0) break;   // C is a fixed point: C_final == sC
    }

    // ---- fused final pass: argmax(P'*C_final), argmax(P') (== argmin d), finiteness ----
#pragma unroll
    for (int rr = 0; rr < 16; ++rr) {
        int row = r0 + w * 16 + rr;
        const float* pr = g_P + (size_t)row * NCOL;
        float rb = sR[w * 16 + rr] * 32768.0f;

        float bq = -FLT_MAX; int biq = 0;
        float bp = -FLT_MAX; int bip = 0;
        bool bad = false;
#pragma unroll
        for (int q = 0; q < 4; ++q) {
            F8 p = (rr < 11) ? ldg_evl8(pr + lane * 8 + 256 * q)
                             : ldg_cs8(pr + lane * 8 + 256 * q);
            const float* cv = sC + lane * 8 + 256 * q;
            int jb = lane * 8 + 256 * q;
#pragma unroll
            for (int e = 0; e < 8; ++e) {
                float qv = p.f[e] * cv[e];
                float full = qv * rb;
                if (!(fabsf(full) <= FLT_MAX)) bad = true;
                if (qv > bq) { bq = qv; biq = jb + e; }
                if (p.f[e] > bp) { bp = p.f[e]; bip = jb + e; }
            }
        }
#pragma unroll
        for (int o = 16; o; o >>= 1) {
            float ov = __shfl_xor_sync(0xffffffffu, bq, o);
            int   oi = __shfl_xor_sync(0xffffffffu, biq, o);
            if (ov > bq || (ov == bq && oi < biq)) { bq = ov; biq = oi; }
            ov = __shfl_xor_sync(0xffffffffu, bp, o);
            oi = __shfl_xor_sync(0xffffffffu, bip, o);
            if (ov > bp || (ov == bp && oi < bip)) { bp = ov; bip = oi; }
        }
        bool anybad = __any_sync(0xffffffffu, bad);
        if (lane == 0) {
            g_idxQ[row] = biq;
            g_idxD[row] = bip;
            if (anybad) atomicOr(&g_bad, 1);
        }
    }
}

// ---------------- output: x_q_st rows, indices, loss (fused last-block reduce) -----------
__global__ void k_output(const float* __restrict__ x, const float* __restrict__ W,
                         float* __restrict__ out) {
    __shared__ float spart[8];
    __shared__ float sred[256];
    __shared__ int   slast;
    int tid = threadIdx.x, lane = tid & 31, w = tid >> 5;
    int row = blockIdx.x * 8 + w;
    int idx = g_bad ? g_idxD[row] : g_idxQ[row];

    float2 wv = ((const float2*)(W + (size_t)idx * DIM))[lane];
    float2 xv = ((const float2*)(x + (size_t)row * DIM))[lane];
    float dx = wv.x - xv.x, dy = wv.y - xv.y;
    float2 st = make_float2(xv.x + dx, xv.y + dy);   // x + (x_q - x)
    ((float2*)(out + (size_t)row * DIM))[lane] = st;

    float s = dx * dx + dy * dy;
#pragma unroll
    for (int o = 16; o; o >>= 1) s += __shfl_xor_sync(0xffffffffu, s, o);
    if (lane == 0) {
        spart[w] = s;
        out[IDX_OFF + row] = (float)idx;
    }
    __syncthreads();
    if (tid == 0) {
        float t = 0.f;
#pragma unroll
        for (int i = 0; i < 8; ++i) t += spart[i];
        g_losspart[blockIdx.x] = t;
        __threadfence();
        slast = (atomicAdd(&g_outcnt, 1) == 4095) ? 1 : 0;
    }
    __syncthreads();

    if (slast) {
        float acc = 0.f;
        for (int i = tid; i < 4096; i += 256) acc += __ldcg(&g_losspart[i]);
        sred[tid] = acc;
        __syncthreads();
        for (int o = 128; o; o >>= 1) {
            if (tid < o) sred[tid] += sred[tid + o];
            __syncthreads();
        }
        if (tid == 0) {
            float m = sred[0] / (float)XQ_ELEMS;
            out[LOSS_OFF] = m + 0.25f * m;
            g_outcnt = 0;                 // reset for next graph replay
        }
    }
}

extern "C" void kernel_launch(void* const* d_in, const int* in_sizes, int n_in,
                              void* d_out, int out_size) {
    const float* x = (const float*)d_in[0];
    const float* W = (const float*)d_in[1];
    float* out = (float*)d_out;

    static bool attr_set = false;
    if (!attr_set) {
        cudaFuncSetAttribute(k_sink, cudaFuncAttributeMaxDynamicSharedMemorySize,
                             SINK_SMEM_BYTES);
        attr_set = true;
    }

    k_init0<<<4624, 256>>>(x, W);
    k_gemm<<<dim3(512, 16), 256>>>(x, W);
    k_sink<<<SINK_BLOCKS, 512, SINK_SMEM_BYTES>>>();
    k_output<<<4096, 256>>>(x, W, out);
}

// round 11
// speedup vs baseline: 1.0464x; 1.0248x over previous
#include <cuda_runtime.h>
#include <cstdint>
#include <cfloat>

#define NROW 32768
#define NCOL 1024
#define DIM 64
#define ITERS 100
#define SINK_BLOCKS 128
#define XQ_ELEMS (NROW * DIM)          // 2097152
#define LOSS_OFF XQ_ELEMS
#define IDX_OFF (XQ_ELEMS + 1)

// k_sink dynamic smem: sC[1024] | sacc[16*1024] | sR[256] | sTrash[16]
#define SINK_SMEM_FLOATS (1024 + 16 * 1024 + 256 + 16)
#define SINK_SMEM_BYTES (SINK_SMEM_FLOATS * 4)   // 70720

// ---------------- device scratch (static: no runtime allocation) ----------------
__device__ float    g_P[(size_t)NROW * NCOL];     // d, then P' = exp(sc*(middle-d)); 134MB
__device__ float    g_xx[NROW];
__device__ float    g_ww[NCOL];
__device__ float    g_colsum[ITERS][NCOL];        // per-iteration column sums
__device__ int      g_idxQ[NROW];
__device__ int      g_idxD[NROW];
__device__ int      g_bad;
__device__ float    g_losspart[4096];
__device__ unsigned g_dmin_u, g_dmax_u;
__device__ unsigned g_barrier;
__device__ int      g_outcnt;

__device__ __forceinline__ unsigned fmapu(float f) {
    unsigned u = __float_as_uint(f);
    return (u & 0x80000000u) ? ~u : (u | 0x80000000u);
}
__device__ __forceinline__ float funmap(unsigned m) {
    unsigned v = (m & 0x80000000u) ? (m & 0x7fffffffu) : ~m;
    return __uint_as_float(v);
}

// FFMA-only exp (no MUFU). Identical to all passing rounds.
__device__ __forceinline__ float fexp(float x) {
    float t = x * 1.4426950408889634f;
    float r = rintf(t);
    float g = (t - r) * 0.6931471805599453f;
    float p = 1.0f + g * (1.0f + g * (0.5f + g * (0.16666666667f +
              g * (0.041666666667f + g * (0.0083333333333f + g * 0.0013888888889f)))));
    int ir = (int)r;
    float s = __int_as_float((ir + 127) << 23);
    return p * s;
}

// ---------------- 32-byte access helpers ----------------
struct F8 { float f[8]; };

__device__ __forceinline__ F8 ldg_evl8(const float* p) {   // keep in L2
    unsigned long long a, b, c, d;
    asm volatile("ld.global.nc.L2::evict_last.v4.b64 {%0,%1,%2,%3}, [%4];"
                 : "=l"(a), "=l"(b), "=l"(c), "=l"(d) : "l"(p));
    F8 r;
    r.f[0] = __uint_as_float((unsigned)a); r.f[1] = __uint_as_float((unsigned)(a >> 32));
    r.f[2] = __uint_as_float((unsigned)b); r.f[3] = __uint_as_float((unsigned)(b >> 32));
    r.f[4] = __uint_as_float((unsigned)c); r.f[5] = __uint_as_float((unsigned)(c >> 32));
    r.f[6] = __uint_as_float((unsigned)d); r.f[7] = __uint_as_float((unsigned)(d >> 32));
    return r;
}
__device__ __forceinline__ F8 ldg_cs8(const float* p) {    // stream through L2
    F8 r;
    float4 a = __ldcs((const float4*)p);
    float4 b = __ldcs((const float4*)p + 1);
    r.f[0] = a.x; r.f[1] = a.y; r.f[2] = a.z; r.f[3] = a.w;
    r.f[4] = b.x; r.f[5] = b.y; r.f[6] = b.z; r.f[7] = b.w;
    return r;
}
__device__ __forceinline__ void stg_evl8(float* p, const F8& v) {
    unsigned long long a = (unsigned long long)__float_as_uint(v.f[0]) |
                           ((unsigned long long)__float_as_uint(v.f[1]) << 32);
    unsigned long long b = (unsigned long long)__float_as_uint(v.f[2]) |
                           ((unsigned long long)__float_as_uint(v.f[3]) << 32);
    unsigned long long c = (unsigned long long)__float_as_uint(v.f[4]) |
                           ((unsigned long long)__float_as_uint(v.f[5]) << 32);
    unsigned long long d = (unsigned long long)__float_as_uint(v.f[6]) |
                           ((unsigned long long)__float_as_uint(v.f[7]) << 32);
    asm volatile("st.global.L2::evict_last.v4.b64 [%0], {%1,%2,%3,%4};"
                 :: "l"(p), "l"(a), "l"(b), "l"(c), "l"(d) : "memory");
}
__device__ __forceinline__ void stg_cs8(float* p, const F8& v) {
    __stcs((float4*)p,     make_float4(v.f[0], v.f[1], v.f[2], v.f[3]));
    __stcs((float4*)p + 1, make_float4(v.f[4], v.f[5], v.f[6], v.f[7]));
}

// ---------------- init: norms + colsum zero + scalars ----------------
__global__ void k_init0(const float* __restrict__ x, const float* __restrict__ W) {
    int tid = threadIdx.x;
    if (blockIdx.x < 4224) {
        int gw = blockIdx.x * 8 + (tid >> 5);
        int lane = tid & 31;
        if (gw >= NROW + NCOL) return;
        const float* src = (gw < NROW) ? (x + (size_t)gw * DIM)
                                       : (W + (size_t)(gw - NROW) * DIM);
        float2 v = ((const float2*)src)[lane];
        float s = v.x * v.x + v.y * v.y;
#pragma unroll
        for (int o = 16; o; o >>= 1) s += __shfl_xor_sync(0xffffffffu, s, o);
        if (lane == 0) {
            if (gw < NROW) g_xx[gw] = s;
            else           g_ww[gw - NROW] = s;
        }
    } else {
        int i = (blockIdx.x - 4224) * 256 + tid;
        if (i < ITERS * NCOL) ((float*)g_colsum)[i] = 0.0f;
        if (blockIdx.x == 4224 && tid == 0) {
            g_barrier = 0u;
            g_bad = 0;
            g_outcnt = 0;
            g_dmin_u = 0xFFFFFFFFu;
            g_dmax_u = 0u;
        }
    }
}

// ---------------- d = xx + ww - 2 x@W^T; global min/max of d ----------------
__global__ void __launch_bounds__(256) k_gemm(const float* __restrict__ x,
                                              const float* __restrict__ W) {
    __shared__ float xsT[64][68];
    __shared__ float wsT[64][68];
    int tid = threadIdx.x;
    int r0 = blockIdx.x * 64;
    int c0 = blockIdx.y * 64;

    for (int n = tid; n < 1024; n += 256) {
        int r = n >> 4, d4 = (n & 15) << 2;
        float4 v = *(const float4*)(x + (size_t)(r0 + r) * DIM + d4);
        xsT[d4 + 0][r] = v.x; xsT[d4 + 1][r] = v.y;
        xsT[d4 + 2][r] = v.z; xsT[d4 + 3][r] = v.w;
        float4 u = *(const float4*)(W + (size_t)(c0 + r) * DIM + d4);
        wsT[d4 + 0][r] = u.x; wsT[d4 + 1][r] = u.y;
        wsT[d4 + 2][r] = u.z; wsT[d4 + 3][r] = u.w;
    }
    __syncthreads();

    int tx = tid & 15, ty = tid >> 4;
    float acc[4][4];
#pragma unroll
    for (int i = 0; i < 4; ++i)
#pragma unroll
        for (int j = 0; j < 4; ++j) acc[i][j] = 0.0f;

#pragma unroll 8
    for (int d = 0; d < 64; ++d) {
        float4 a = *(const float4*)&xsT[d][ty * 4];
        float4 b = *(const float4*)&wsT[d][tx * 4];
        float av[4] = {a.x, a.y, a.z, a.w};
        float bv[4] = {b.x, b.y, b.z, b.w};
#pragma unroll
        for (int i = 0; i < 4; ++i)
#pragma unroll
            for (int j = 0; j < 4; ++j) acc[i][j] += av[i] * bv[j];
    }

    float mn = FLT_MAX, mx = -FLT_MAX;
#pragma unroll
    for (int i = 0; i < 4; ++i) {
        int row = r0 + ty * 4 + i;
        float xxv = g_xx[row];
        float dv[4];
#pragma unroll
        for (int j = 0; j < 4; ++j) {
            dv[j] = (xxv + g_ww[c0 + tx * 4 + j]) - 2.0f * acc[i][j];
            mn = fminf(mn, dv[j]);
            mx = fmaxf(mx, dv[j]);
        }
        *(float4*)(g_P + (size_t)row * NCOL + c0 + tx * 4) =
            make_float4(dv[0], dv[1], dv[2], dv[3]);
    }

    __shared__ float smn[256], smx[256];
    smn[tid] = mn; smx[tid] = mx;
    __syncthreads();
    for (int s = 128; s; s >>= 1) {
        if (tid < s) {
            smn[tid] = fminf(smn[tid], smn[tid + s]);
            smx[tid] = fmaxf(smx[tid], smx[tid + s]);
        }
        __syncthreads();
    }
    if (tid == 0) {
        atomicMin(&g_dmin_u, fmapu(smn[0]));
        atomicMax(&g_dmax_u, fmapu(smx[0]));
    }
}

// ---------------- persistent Sinkhorn (R7 structure, short dot chains) ----------------
// Block owns 256 contiguous rows; warp w owns rows [16w, 16w+16).
//   (row mod 16) < 11 : pinned in L2 (evict_last, 88MB chip-wide)
//   else              : streamed (.cs, 46MB DRAM/iter)
// Hot loop: row pairs (8 loads in flight), dots split into 4 independent per-q
// partial chains per row (8 interleavable 8-FFMA chains per pair), interleaved
// shuffle reductions.
__global__ void __launch_bounds__(512, 1) k_sink() {
    extern __shared__ float sm[];
    float* sC     = sm;                      // [1024]
    float* sacc   = sm + 1024;               // [16][1024] per-warp column partials
    float* sR     = sm + 1024 + 16 * 1024;   // [256] last-iter row factors
    float* sTrash = sR + 256;                // [16] never-taken sink

    int tid = threadIdx.x, lane = tid & 31, w = tid >> 5;
    int r0 = blockIdx.x * 256;
    unsigned phase = 0;

    // constants derived redundantly per block (k_gemm completed before launch)
    float mnv = funmap(g_dmin_u);
    float mxv = funmap(g_dmax_u);
    float mid = (mxv + mnv) * 0.5f;
    float sc = 1.0f / ((mxv - mid + 1e-5f) * 0.05f);

    for (int j = tid; j < NCOL; j += 512) sC[j] = 1.0f;   // C^(0) = 1
    __syncthreads();

    F8 racc[4];
#pragma unroll
    for (int q = 0; q < 4; ++q)
#pragma unroll
        for (int e = 0; e < 8; ++e) racc[q].f[e] = 0.0f;

    // ---- pre-phase == transform + iteration 0 (C=1): read d, P'=fexp, store, dot ----
#pragma unroll
    for (int rr = 0; rr < 16; ++rr) {
        int row = r0 + w * 16 + rr;
        float* pr = g_P + (size_t)row * NCOL;
        F8 p[4];
#pragma unroll
        for (int q = 0; q < 4; ++q) {
            F8 v = ldg_cs8(pr + lane * 8 + 256 * q);
#pragma unroll
            for (int e = 0; e < 8; ++e) v.f[e] = fexp((mid - v.f[e]) * sc);
            p[q] = v;
        }
        if (rr < 11) {
#pragma unroll
            for (int q = 0; q < 4; ++q) stg_evl8(pr + lane * 8 + 256 * q, p[q]);
        } else {
#pragma unroll
            for (int q = 0; q < 4; ++q) stg_cs8(pr + lane * 8 + 256 * q, p[q]);
        }
        float dq[4];
#pragma unroll
        for (int q = 0; q < 4; ++q)
            dq[q] = p[q].f[0] + p[q].f[1] + p[q].f[2] + p[q].f[3]
                  + p[q].f[4] + p[q].f[5] + p[q].f[6] + p[q].f[7];
        float dot = (dq[0] + dq[1]) + (dq[2] + dq[3]);
#pragma unroll
        for (int o = 16; o; o >>= 1) dot += __shfl_xor_sync(0xffffffffu, dot, o);
        float R = 1.0f / (32768.0f * dot);
#pragma unroll
        for (int q = 0; q < 4; ++q)
#pragma unroll
            for (int e = 0; e < 8; ++e) racc[q].f[e] += R * p[q].f[e];
        if (lane == 0) sR[w * 16 + rr] = R;
    }

    // ---- iterations; t==0 uses the pre-phase racc ----
    for (int t = 0; t < ITERS; ++t) {
        if (t > 0) {
#pragma unroll
            for (int q = 0; q < 4; ++q)
#pragma unroll
                for (int e = 0; e < 8; ++e) racc[q].f[e] = 0.0f;

#pragma unroll
            for (int rp = 0; rp < 8; ++rp) {            // row PAIRS (2*rp, 2*rp+1)
                int ra = r0 + w * 16 + 2 * rp;
                const float* pa = g_P + (size_t)ra * NCOL;
                const float* pb = pa + NCOL;
                F8 A[4], B[4];
#pragma unroll
                for (int q = 0; q < 4; ++q) {
                    if (2 * rp < 11)     A[q] = ldg_evl8(pa + lane * 8 + 256 * q);
                    else                 A[q] = ldg_cs8(pa + lane * 8 + 256 * q);
                    if (2 * rp + 1 < 11) B[q] = ldg_evl8(pb + lane * 8 + 256 * q);
                    else                 B[q] = ldg_cs8(pb + lane * 8 + 256 * q);
                }
                // 4 independent partial chains per row (8 chains total, interleavable)
                float dA[4], dB[4];
#pragma unroll
                for (int q = 0; q < 4; ++q) {
                    const float* cv = sC + lane * 8 + 256 * q;
                    float4 c0 = *(const float4*)cv;
                    float4 c1 = *(const float4*)(cv + 4);
                    dA[q] = A[q].f[0] * c0.x + A[q].f[1] * c0.y + A[q].f[2] * c0.z + A[q].f[3] * c0.w
                          + A[q].f[4] * c1.x + A[q].f[5] * c1.y + A[q].f[6] * c1.z + A[q].f[7] * c1.w;
                    dB[q] = B[q].f[0] * c0.x + B[q].f[1] * c0.y + B[q].f[2] * c0.z + B[q].f[3] * c0.w
                          + B[q].f[4] * c1.x + B[q].f[5] * c1.y + B[q].f[6] * c1.z + B[q].f[7] * c1.w;
                }
                float dota = (dA[0] + dA[1]) + (dA[2] + dA[3]);
                float dotb = (dB[0] + dB[1]) + (dB[2] + dB[3]);
#pragma unroll
                for (int o = 16; o; o >>= 1) {
                    dota += __shfl_xor_sync(0xffffffffu, dota, o);
                    dotb += __shfl_xor_sync(0xffffffffu, dotb, o);
                }
                float Ra = 1.0f / (32768.0f * dota);
                float Rb = 1.0f / (32768.0f * dotb);
#pragma unroll
                for (int q = 0; q < 4; ++q)
#pragma unroll
                    for (int e = 0; e < 8; ++e) racc[q].f[e] += Ra * A[q].f[e];
#pragma unroll
                for (int q = 0; q < 4; ++q)
#pragma unroll
                    for (int e = 0; e < 8; ++e) racc[q].f[e] += Rb * B[q].f[e];
                if (lane == 0) {
                    sR[w * 16 + 2 * rp]     = Ra;
                    sR[w * 16 + 2 * rp + 1] = Rb;
                }
            }
        }

        // deterministic staged reduction: warp partials -> smem -> global RED
#pragma unroll
        for (int q = 0; q < 4; ++q) {
            float* dst = sacc + w * NCOL + lane * 8 + 256 * q;
            *(float4*)dst       = make_float4(racc[q].f[0], racc[q].f[1], racc[q].f[2], racc[q].f[3]);
            *(float4*)(dst + 4) = make_float4(racc[q].f[4], racc[q].f[5], racc[q].f[6], racc[q].f[7]);
        }
        __syncthreads();
        float dummy = 0.0f;
        for (int j = tid; j < NCOL; j += 512) {
            float s = 0.0f;
#pragma unroll
            for (int ww = 0; ww < 16; ++ww) s += sacc[ww * NCOL + j];
            dummy += atomicAdd(&g_colsum[t][j], s);
        }
        // completion fence: consuming atomic returns guarantees REDs performed at L2
        if (__float_as_uint(dummy) == 0x7F800123u) sTrash[w] = dummy;
        __syncthreads();
        if (tid == 0) {
            unsigned arrived = atomicAdd(&g_barrier, 1u) + 1u;
            phase += SINK_BLOCKS;
            if (arrived < phase) {
                while (*(volatile unsigned*)&g_barrier < phase) __nanosleep(32);
            }
        }
        __syncthreads();

        for (int j = tid; j < NCOL; j += 512)
            sC[j] = 1.0f / (1024.0f * __ldcg(&g_colsum[t][j]));
        __syncthreads();
    }

    // ---- fused final pass: argmax(P'*C_final), argmax(P') (== argmin d), finiteness ----
#pragma unroll
    for (int rr = 0; rr < 16; ++rr) {
        int row = r0 + w * 16 + rr;
        const float* pr = g_P + (size_t)row * NCOL;
        float rb = sR[w * 16 + rr] * 32768.0f;

        float bq = -FLT_MAX; int biq = 0;
        float bp = -FLT_MAX; int bip = 0;
        bool bad = false;
#pragma unroll
        for (int q = 0; q < 4; ++q) {
            F8 p = (rr < 11) ? ldg_evl8(pr + lane * 8 + 256 * q)
                             : ldg_cs8(pr + lane * 8 + 256 * q);
            const float* cv = sC + lane * 8 + 256 * q;
            int jb = lane * 8 + 256 * q;
#pragma unroll
            for (int e = 0; e < 8; ++e) {
                float qv = p.f[e] * cv[e];
                float full = qv * rb;
                if (!(fabsf(full) <= FLT_MAX)) bad = true;
                if (qv > bq) { bq = qv; biq = jb + e; }
                if (p.f[e] > bp) { bp = p.f[e]; bip = jb + e; }
            }
        }
#pragma unroll
        for (int o = 16; o; o >>= 1) {
            float ov = __shfl_xor_sync(0xffffffffu, bq, o);
            int   oi = __shfl_xor_sync(0xffffffffu, biq, o);
            if (ov > bq || (ov == bq && oi < biq)) { bq = ov; biq = oi; }
            ov = __shfl_xor_sync(0xffffffffu, bp, o);
            oi = __shfl_xor_sync(0xffffffffu, bip, o);
            if (ov > bp || (ov == bp && oi < bip)) { bp = ov; bip = oi; }
        }
        bool anybad = __any_sync(0xffffffffu, bad);
        if (lane == 0) {
            g_idxQ[row] = biq;
            g_idxD[row] = bip;
            if (anybad) atomicOr(&g_bad, 1);
        }
    }
}

// ---------------- output: x_q_st rows, indices, loss (fused last-block reduce) -----------
__global__ void k_output(const float* __restrict__ x, const float* __restrict__ W,
                         float* __restrict__ out) {
    __shared__ float spart[8];
    __shared__ float sred[256];
    __shared__ int   slast;
    int tid = threadIdx.x, lane = tid & 31, w = tid >> 5;
    int row = blockIdx.x * 8 + w;
    int idx = g_bad ? g_idxD[row] : g_idxQ[row];

    float2 wv = ((const float2*)(W + (size_t)idx * DIM))[lane];
    float2 xv = ((const float2*)(x + (size_t)row * DIM))[lane];
    float dx = wv.x - xv.x, dy = wv.y - xv.y;
    float2 st = make_float2(xv.x + dx, xv.y + dy);   // x + (x_q - x)
    ((float2*)(out + (size_t)row * DIM))[lane] = st;

    float s = dx * dx + dy * dy;
#pragma unroll
    for (int o = 16; o; o >>= 1) s += __shfl_xor_sync(0xffffffffu, s, o);
    if (lane == 0) {
        spart[w] = s;
        out[IDX_OFF + row] = (float)idx;
    }
    __syncthreads();
    if (tid == 0) {
        float t = 0.f;
#pragma unroll
        for (int i = 0; i < 8; ++i) t += spart[i];
        g_losspart[blockIdx.x] = t;
        __threadfence();
        slast = (atomicAdd(&g_outcnt, 1) == 4095) ? 1 : 0;
    }
    __syncthreads();

    if (slast) {
        float acc = 0.f;
        for (int i = tid; i < 4096; i += 256) acc += __ldcg(&g_losspart[i]);
        sred[tid] = acc;
        __syncthreads();
        for (int o = 128; o; o >>= 1) {
            if (tid < o) sred[tid] += sred[tid + o];
            __syncthreads();
        }
        if (tid == 0) {
            float m = sred[0] / (float)XQ_ELEMS;
            out[LOSS_OFF] = m + 0.25f * m;
            g_outcnt = 0;                 // reset for next graph replay
        }
    }
}

extern "C" void kernel_launch(void* const* d_in, const int* in_sizes, int n_in,
                              void* d_out, int out_size) {
    const float* x = (const float*)d_in[0];
    const float* W = (const float*)d_in[1];
    float* out = (float*)d_out;

    static bool attr_set = false;
    if (!attr_set) {
        cudaFuncSetAttribute(k_sink, cudaFuncAttributeMaxDynamicSharedMemorySize,
                             SINK_SMEM_BYTES);
        attr_set = true;
    }

    k_init0<<<4624, 256>>>(x, W);
    k_gemm<<<dim3(512, 16), 256>>>(x, W);
    k_sink<<<SINK_BLOCKS, 512, SINK_SMEM_BYTES>>>();
    k_output<<<4096, 256>>>(x, W, out);
}

// round 12
// speedup vs baseline: 1.0828x; 1.0347x over previous
#include <cuda_runtime.h>
#include <cstdint>
#include <cfloat>

#define NROW 32768
#define NCOL 1024
#define DIM 64
#define ITERS 100
#define SINK_BLOCKS 128
#define XQ_ELEMS (NROW * DIM)          // 2097152
#define LOSS_OFF XQ_ELEMS
#define IDX_OFF (XQ_ELEMS + 1)

// k_sink dynamic smem: sC[1024] | sacc[16*1024] | sR[256] | sTrash[16]
#define SINK_SMEM_FLOATS (1024 + 16 * 1024 + 256 + 16)
#define SINK_SMEM_BYTES (SINK_SMEM_FLOATS * 4)   // 70720

// ---------------- device scratch (static: no runtime allocation) ----------------
__device__ float    g_P[(size_t)NROW * NCOL];     // d, then P' = exp(sc*(middle-d)); 134MB
__device__ float    g_xx[NROW];
__device__ float    g_ww[NCOL];
__device__ float    g_colsum[ITERS][NCOL];        // per-iteration column sums
__device__ int      g_idxQ[NROW];
__device__ int      g_idxD[NROW];
__device__ int      g_bad;
__device__ float    g_losspart[4096];
__device__ unsigned g_dmin_u, g_dmax_u;
__device__ unsigned g_barrier;
__device__ int      g_outcnt;

__device__ __forceinline__ unsigned fmapu(float f) {
    unsigned u = __float_as_uint(f);
    return (u & 0x80000000u) ? ~u : (u | 0x80000000u);
}
__device__ __forceinline__ float funmap(unsigned m) {
    unsigned v = (m & 0x80000000u) ? (m & 0x7fffffffu) : ~m;
    return __uint_as_float(v);
}

// ---------------- packed f32x2 helpers (Blackwell FFMA2 path) ----------------
typedef unsigned long long u64t;

__device__ __forceinline__ u64t fma2(u64t a, u64t b, u64t c) {
    u64t d;
    asm("fma.rn.f32x2 %0, %1, %2, %3;" : "=l"(d) : "l"(a), "l"(b), "l"(c));
    return d;
}
__device__ __forceinline__ u64t add2(u64t a, u64t b) {
    u64t d;
    asm("add.rn.f32x2 %0, %1, %2;" : "=l"(d) : "l"(a), "l"(b));
    return d;
}
__device__ __forceinline__ float2 unpk(u64t v) {
    float2 f;
    asm("mov.b64 {%0, %1}, %2;" : "=f"(f.x), "=f"(f.y) : "l"(v));
    return f;
}
__device__ __forceinline__ u64t pk2(float lo, float hi) {
    u64t v;
    asm("mov.b64 %0, {%1, %2};" : "=l"(v) : "f"(lo), "f"(hi));
    return v;
}

// ---------------- 32-byte access helpers ----------------
struct F8 { float f[8]; };            // scalar view (final pass)
struct U8 { u64t u[4]; };             // packed view (hot loop)

__device__ __forceinline__ F8 ldg_evl8(const float* p) {   // keep in L2, scalar out
    u64t a, b, c, d;
    asm volatile("ld.global.nc.L2::evict_last.v4.b64 {%0,%1,%2,%3}, [%4];"
                 : "=l"(a), "=l"(b), "=l"(c), "=l"(d) : "l"(p));
    F8 r;
    r.f[0] = __uint_as_float((unsigned)a); r.f[1] = __uint_as_float((unsigned)(a >> 32));
    r.f[2] = __uint_as_float((unsigned)b); r.f[3] = __uint_as_float((unsigned)(b >> 32));
    r.f[4] = __uint_as_float((unsigned)c); r.f[5] = __uint_as_float((unsigned)(c >> 32));
    r.f[6] = __uint_as_float((unsigned)d); r.f[7] = __uint_as_float((unsigned)(d >> 32));
    return r;
}
__device__ __forceinline__ F8 ldg_cs8(const float* p) {    // stream, scalar out
    F8 r;
    float4 a = __ldcs((const float4*)p);
    float4 b = __ldcs((const float4*)p + 1);
    r.f[0] = a.x; r.f[1] = a.y; r.f[2] = a.z; r.f[3] = a.w;
    r.f[4] = b.x; r.f[5] = b.y; r.f[6] = b.z; r.f[7] = b.w;
    return r;
}
__device__ __forceinline__ U8 ldg_evl8p(const float* p) {  // keep in L2, packed out
    U8 r;
    asm volatile("ld.global.nc.L2::evict_last.v4.b64 {%0,%1,%2,%3}, [%4];"
                 : "=l"(r.u[0]), "=l"(r.u[1]), "=l"(r.u[2]), "=l"(r.u[3]) : "l"(p));
    return r;
}
__device__ __forceinline__ U8 ldg_evf8p(const float* p) {  // stream, packed out
    U8 r;
    asm volatile("ld.global.nc.L2::evict_first.v4.b64 {%0,%1,%2,%3}, [%4];"
                 : "=l"(r.u[0]), "=l"(r.u[1]), "=l"(r.u[2]), "=l"(r.u[3]) : "l"(p));
    return r;
}
__device__ __forceinline__ void stg_evl8p(float* p, const U8& v) {
    asm volatile("st.global.L2::evict_last.v4.b64 [%0], {%1,%2,%3,%4};"
                 :: "l"(p), "l"(v.u[0]), "l"(v.u[1]), "l"(v.u[2]), "l"(v.u[3]) : "memory");
}
__device__ __forceinline__ void stg_evf8p(float* p, const U8& v) {
    asm volatile("st.global.L2::evict_first.v4.b64 [%0], {%1,%2,%3,%4};"
                 :: "l"(p), "l"(v.u[0]), "l"(v.u[1]), "l"(v.u[2]), "l"(v.u[3]) : "memory");
}

// ---------------- init: norms + colsum zero + scalars ----------------
__global__ void k_init0(const float* __restrict__ x, const float* __restrict__ W) {
    int tid = threadIdx.x;
    if (blockIdx.x < 4224) {
        int gw = blockIdx.x * 8 + (tid >> 5);
        int lane = tid & 31;
        if (gw >= NROW + NCOL) return;
        const float* src = (gw < NROW) ? (x + (size_t)gw * DIM)
                                       : (W + (size_t)(gw - NROW) * DIM);
        float2 v = ((const float2*)src)[lane];
        float s = v.x * v.x + v.y * v.y;
#pragma unroll
        for (int o = 16; o; o >>= 1) s += __shfl_xor_sync(0xffffffffu, s, o);
        if (lane == 0) {
            if (gw < NROW) g_xx[gw] = s;
            else           g_ww[gw - NROW] = s;
        }
    } else {
        int i = (blockIdx.x - 4224) * 256 + tid;
        if (i < ITERS * NCOL) ((float*)g_colsum)[i] = 0.0f;
        if (blockIdx.x == 4224 && tid == 0) {
            g_barrier = 0u;
            g_bad = 0;
            g_outcnt = 0;
            g_dmin_u = 0xFFFFFFFFu;
            g_dmax_u = 0u;
        }
    }
}

// ---------------- d = xx + ww - 2 x@W^T; global min/max of d ----------------
__global__ void __launch_bounds__(256) k_gemm(const float* __restrict__ x,
                                              const float* __restrict__ W) {
    __shared__ float xsT[64][68];
    __shared__ float wsT[64][68];
    int tid = threadIdx.x;
    int r0 = blockIdx.x * 64;
    int c0 = blockIdx.y * 64;

    for (int n = tid; n < 1024; n += 256) {
        int r = n >> 4, d4 = (n & 15) << 2;
        float4 v = *(const float4*)(x + (size_t)(r0 + r) * DIM + d4);
        xsT[d4 + 0][r] = v.x; xsT[d4 + 1][r] = v.y;
        xsT[d4 + 2][r] = v.z; xsT[d4 + 3][r] = v.w;
        float4 u = *(const float4*)(W + (size_t)(c0 + r) * DIM + d4);
        wsT[d4 + 0][r] = u.x; wsT[d4 + 1][r] = u.y;
        wsT[d4 + 2][r] = u.z; wsT[d4 + 3][r] = u.w;
    }
    __syncthreads();

    int tx = tid & 15, ty = tid >> 4;
    float acc[4][4];
#pragma unroll
    for (int i = 0; i < 4; ++i)
#pragma unroll
        for (int j = 0; j < 4; ++j) acc[i][j] = 0.0f;

#pragma unroll 8
    for (int d = 0; d < 64; ++d) {
        float4 a = *(const float4*)&xsT[d][ty * 4];
        float4 b = *(const float4*)&wsT[d][tx * 4];
        float av[4] = {a.x, a.y, a.z, a.w};
        float bv[4] = {b.x, b.y, b.z, b.w};
#pragma unroll
        for (int i = 0; i < 4; ++i)
#pragma unroll
            for (int j = 0; j < 4; ++j) acc[i][j] += av[i] * bv[j];
    }

    float mn = FLT_MAX, mx = -FLT_MAX;
#pragma unroll
    for (int i = 0; i < 4; ++i) {
        int row = r0 + ty * 4 + i;
        float xxv = g_xx[row];
        float dv[4];
#pragma unroll
        for (int j = 0; j < 4; ++j) {
            dv[j] = (xxv + g_ww[c0 + tx * 4 + j]) - 2.0f * acc[i][j];
            mn = fminf(mn, dv[j]);
            mx = fmaxf(mx, dv[j]);
        }
        *(float4*)(g_P + (size_t)row * NCOL + c0 + tx * 4) =
            make_float4(dv[0], dv[1], dv[2], dv[3]);
    }

    __shared__ float smn[256], smx[256];
    smn[tid] = mn; smx[tid] = mx;
    __syncthreads();
    for (int s = 128; s; s >>= 1) {
        if (tid < s) {
            smn[tid] = fminf(smn[tid], smn[tid + s]);
            smx[tid] = fmaxf(smx[tid], smx[tid + s]);
        }
        __syncthreads();
    }
    if (tid == 0) {
        atomicMin(&g_dmin_u, fmapu(smn[0]));
        atomicMax(&g_dmax_u, fmapu(smx[0]));
    }
}

// ---------------- persistent Sinkhorn (R11 structure, FFMA2 hot loop) ----------------
// Block owns 256 contiguous rows; warp w owns rows [16w, 16w+16).
//   (row mod 16) < 11 : pinned in L2 (evict_last, 88MB chip-wide)
//   else              : streamed (evict_first, 46MB DRAM/iter)
__global__ void __launch_bounds__(512, 1) k_sink() {
    extern __shared__ float sm[];
    float* sC     = sm;                      // [1024]
    float* sacc   = sm + 1024;               // [16][1024] per-warp column partials
    float* sR     = sm + 1024 + 16 * 1024;   // [256] last-iter row factors
    float* sTrash = sR + 256;                // [16] never-taken sink

    int tid = threadIdx.x, lane = tid & 31, w = tid >> 5;
    int r0 = blockIdx.x * 256;
    unsigned phase = 0;

    // constants derived redundantly per block (k_gemm completed before launch)
    float mnv = funmap(g_dmin_u);
    float mxv = funmap(g_dmax_u);
    float mid = (mxv + mnv) * 0.5f;
    float sc = 1.0f / ((mxv - mid + 1e-5f) * 0.05f);

    for (int j = tid; j < NCOL; j += 512) sC[j] = 1.0f;   // C^(0) = 1
    __syncthreads();

    u64t racc2[16];
#pragma unroll
    for (int i = 0; i < 16; ++i) racc2[i] = 0ULL;

    // ---- pre-phase == transform + iteration 0 (C=1): read d, P'=exp, store, dot ----
#pragma unroll
    for (int rr = 0; rr < 16; ++rr) {
        int row = r0 + w * 16 + rr;
        float* pr = g_P + (size_t)row * NCOL;
        U8 p[4];
#pragma unroll
        for (int q = 0; q < 4; ++q) {
            U8 v = ldg_evf8p(pr + lane * 8 + 256 * q);
#pragma unroll
            for (int k = 0; k < 4; ++k) {
                float2 e = unpk(v.u[k]);
                e.x = __expf((mid - e.x) * sc);
                e.y = __expf((mid - e.y) * sc);
                v.u[k] = pk2(e.x, e.y);
            }
            p[q] = v;
        }
        if (rr < 11) {
#pragma unroll
            for (int q = 0; q < 4; ++q) stg_evl8p(pr + lane * 8 + 256 * q, p[q]);
        } else {
#pragma unroll
            for (int q = 0; q < 4; ++q) stg_evf8p(pr + lane * 8 + 256 * q, p[q]);
        }
        u64t s2 = 0ULL;
#pragma unroll
        for (int q = 0; q < 4; ++q)
#pragma unroll
            for (int k = 0; k < 4; ++k) s2 = add2(s2, p[q].u[k]);
        float2 sf = unpk(s2);
        float dot = sf.x + sf.y;
#pragma unroll
        for (int o = 16; o; o >>= 1) dot += __shfl_xor_sync(0xffffffffu, dot, o);
        float R = 1.0f / (32768.0f * dot);
        u64t R2 = pk2(R, R);
#pragma unroll
        for (int q = 0; q < 4; ++q)
#pragma unroll
            for (int k = 0; k < 4; ++k)
                racc2[q * 4 + k] = fma2(R2, p[q].u[k], racc2[q * 4 + k]);
        if (lane == 0) sR[w * 16 + rr] = R;
    }

    // ---- iterations; t==0 uses the pre-phase racc ----
    for (int t = 0; t < ITERS; ++t) {
        if (t > 0) {
#pragma unroll
            for (int i = 0; i < 16; ++i) racc2[i] = 0ULL;

#pragma unroll
            for (int rp = 0; rp < 8; ++rp) {            // row PAIRS (2*rp, 2*rp+1)
                int ra = r0 + w * 16 + 2 * rp;
                const float* pa = g_P + (size_t)ra * NCOL;
                const float* pb = pa + NCOL;
                U8 A[4], B[4];
#pragma unroll
                for (int q = 0; q < 4; ++q) {
                    if (2 * rp < 11)     A[q] = ldg_evl8p(pa + lane * 8 + 256 * q);
                    else                 A[q] = ldg_evf8p(pa + lane * 8 + 256 * q);
                    if (2 * rp + 1 < 11) B[q] = ldg_evl8p(pb + lane * 8 + 256 * q);
                    else                 B[q] = ldg_evf8p(pb + lane * 8 + 256 * q);
                }
                // packed dot chains (even/odd halves), both rows interleaved
                u64t da2 = 0ULL, db2 = 0ULL;
                const u64t* c2 = (const u64t*)sC + lane * 4;
#pragma unroll
                for (int q = 0; q < 4; ++q) {
#pragma unroll
                    for (int k = 0; k < 4; ++k) {
                        u64t cv = c2[128 * q + k];
                        da2 = fma2(A[q].u[k], cv, da2);
                        db2 = fma2(B[q].u[k], cv, db2);
                    }
                }
                float2 fa = unpk(da2), fb = unpk(db2);
                float dota = fa.x + fa.y;
                float dotb = fb.x + fb.y;
#pragma unroll
                for (int o = 16; o; o >>= 1) {
                    dota += __shfl_xor_sync(0xffffffffu, dota, o);
                    dotb += __shfl_xor_sync(0xffffffffu, dotb, o);
                }
                float Ra = 1.0f / (32768.0f * dota);
                float Rb = 1.0f / (32768.0f * dotb);
                u64t Ra2 = pk2(Ra, Ra), Rb2 = pk2(Rb, Rb);
#pragma unroll
                for (int q = 0; q < 4; ++q)
#pragma unroll
                    for (int k = 0; k < 4; ++k)
                        racc2[q * 4 + k] = fma2(Ra2, A[q].u[k], racc2[q * 4 + k]);
#pragma unroll
                for (int q = 0; q < 4; ++q)
#pragma unroll
                    for (int k = 0; k < 4; ++k)
                        racc2[q * 4 + k] = fma2(Rb2, B[q].u[k], racc2[q * 4 + k]);
                if (lane == 0) {
                    sR[w * 16 + 2 * rp]     = Ra;
                    sR[w * 16 + 2 * rp + 1] = Rb;
                }
            }
        }

        // stage warp partials to smem (bytes identical to scalar layout)
        {
            u64t* dst = (u64t*)(sacc + w * NCOL) + lane * 4;
#pragma unroll
            for (int q = 0; q < 4; ++q) {
                *(ulonglong2*)(dst + 128 * q)     = make_ulonglong2(racc2[q * 4 + 0], racc2[q * 4 + 1]);
                *(ulonglong2*)(dst + 128 * q + 2) = make_ulonglong2(racc2[q * 4 + 2], racc2[q * 4 + 3]);
            }
        }
        __syncthreads();
        // packed tail reduction: thread handles columns (2*tid, 2*tid+1); per-column
        // ww=0..15 order identical to scalar version
        float dummy = 0.0f;
        {
            u64t s2 = 0ULL;
            const u64t* base = (const u64t*)sacc + tid;
#pragma unroll
            for (int ww = 0; ww < 16; ++ww) s2 = add2(s2, base[ww * 512]);
            float2 sf = unpk(s2);
            dummy += atomicAdd(&g_colsum[t][2 * tid],     sf.x);
            dummy += atomicAdd(&g_colsum[t][2 * tid + 1], sf.y);
        }
        // completion fence: consuming atomic returns guarantees REDs performed at L2
        if (__float_as_uint(dummy) == 0x7F800123u) sTrash[w] = dummy;
        __syncthreads();
        if (tid == 0) {
            unsigned arrived = atomicAdd(&g_barrier, 1u) + 1u;
            phase += SINK_BLOCKS;
            if (arrived < phase) {
                while (*(volatile unsigned*)&g_barrier < phase) __nanosleep(32);
            }
        }
        __syncthreads();

        for (int j = tid; j < NCOL; j += 512)
            sC[j] = 1.0f / (1024.0f * __ldcg(&g_colsum[t][j]));
        __syncthreads();
    }

    // ---- fused final pass: argmax(P'*C_final), argmax(P') (== argmin d), finiteness ----
#pragma unroll
    for (int rr = 0; rr < 16; ++rr) {
        int row = r0 + w * 16 + rr;
        const float* pr = g_P + (size_t)row * NCOL;
        float rb = sR[w * 16 + rr] * 32768.0f;

        float bq = -FLT_MAX; int biq = 0;
        float bp = -FLT_MAX; int bip = 0;
        bool bad = false;
#pragma unroll
        for (int q = 0; q < 4; ++q) {
            F8 p = (rr < 11) ? ldg_evl8(pr + lane * 8 + 256 * q)
                             : ldg_cs8(pr + lane * 8 + 256 * q);
            const float* cv = sC + lane * 8 + 256 * q;
            int jb = lane * 8 + 256 * q;
#pragma unroll
            for (int e = 0; e < 8; ++e) {
                float qv = p.f[e] * cv[e];
                float full = qv * rb;
                if (!(fabsf(full) <= FLT_MAX)) bad = true;
                if (qv > bq) { bq = qv; biq = jb + e; }
                if (p.f[e] > bp) { bp = p.f[e]; bip = jb + e; }
            }
        }
#pragma unroll
        for (int o = 16; o; o >>= 1) {
            float ov = __shfl_xor_sync(0xffffffffu, bq, o);
            int   oi = __shfl_xor_sync(0xffffffffu, biq, o);
            if (ov > bq || (ov == bq && oi < biq)) { bq = ov; biq = oi; }
            ov = __shfl_xor_sync(0xffffffffu, bp, o);
            oi = __shfl_xor_sync(0xffffffffu, bip, o);
            if (ov > bp || (ov == bp && oi < bip)) { bp = ov; bip = oi; }
        }
        bool anybad = __any_sync(0xffffffffu, bad);
        if (lane == 0) {
            g_idxQ[row] = biq;
            g_idxD[row] = bip;
            if (anybad) atomicOr(&g_bad, 1);
        }
    }
}

// ---------------- output: x_q_st rows, indices, loss (fused last-block reduce) -----------
__global__ void k_output(const float* __restrict__ x, const float* __restrict__ W,
                         float* __restrict__ out) {
    __shared__ float spart[8];
    __shared__ float sred[256];
    __shared__ int   slast;
    int tid = threadIdx.x, lane = tid & 31, w = tid >> 5;
    int row = blockIdx.x * 8 + w;
    int idx = g_bad ? g_idxD[row] : g_idxQ[row];

    float2 wv = ((const float2*)(W + (size_t)idx * DIM))[lane];
    float2 xv = ((const float2*)(x + (size_t)row * DIM))[lane];
    float dx = wv.x - xv.x, dy = wv.y - xv.y;
    float2 st = make_float2(xv.x + dx, xv.y + dy);   // x + (x_q - x)
    ((float2*)(out + (size_t)row * DIM))[lane] = st;

    float s = dx * dx + dy * dy;
#pragma unroll
    for (int o = 16; o; o >>= 1) s += __shfl_xor_sync(0xffffffffu, s, o);
    if (lane == 0) {
        spart[w] = s;
        out[IDX_OFF + row] = (float)idx;
    }
    __syncthreads();
    if (tid == 0) {
        float t = 0.f;
#pragma unroll
        for (int i = 0; i < 8; ++i) t += spart[i];
        g_losspart[blockIdx.x] = t;
        __threadfence();
        slast = (atomicAdd(&g_outcnt, 1) == 4095) ? 1 : 0;
    }
    __syncthreads();

    if (slast) {
        float acc = 0.f;
        for (int i = tid; i < 4096; i += 256) acc += __ldcg(&g_losspart[i]);
        sred[tid] = acc;
        __syncthreads();
        for (int o = 128; o; o >>= 1) {
            if (tid < o) sred[tid] += sred[tid + o];
            __syncthreads();
        }
        if (tid == 0) {
            float m = sred[0] / (float)XQ_ELEMS;
            out[LOSS_OFF] = m + 0.25f * m;
            g_outcnt = 0;                 // reset for next graph replay
        }
    }
}

extern "C" void kernel_launch(void* const* d_in, const int* in_sizes, int n_in,
                              void* d_out, int out_size) {
    const float* x = (const float*)d_in[0];
    const float* W = (const float*)d_in[1];
    float* out = (float*)d_out;

    static bool attr_set = false;
    if (!attr_set) {
        cudaFuncSetAttribute(k_sink, cudaFuncAttributeMaxDynamicSharedMemorySize,
                             SINK_SMEM_BYTES);
        attr_set = true;
    }

    k_init0<<<4624, 256>>>(x, W);
    k_gemm<<<dim3(512, 16), 256>>>(x, W);
    k_sink<<<SINK_BLOCKS, 512, SINK_SMEM_BYTES>>>();
    k_output<<<4096, 256>>>(x, W, out);
}